// round 13
// baseline (speedup 1.0000x reference)
#include <cuda_runtime.h>
#include <math.h>

#define N 256            // 2B
#define BH 128           // B
#define D 768
#define EPSF 1e-8f
#define INV_TEMP 20.0f   // 1/0.05
#define CNT2 32640.0f    // N(N-1)/2
#define CNT3 16581120.0f // N(N-1)(N-2)

#define SPLITK 16
#define CHUNK 48         // D / SPLITK
#define TSTEP 16         // k per smem stage
#define NSTAGE (CHUNK / TSTEP)   // 3

#define NTILE 10         // symmetric 4x4 -> 10 tiles (bx <= by)
#define NFB 512          // fused grid: 64 j-quads x 8 i-combs

// ---------------- scratch (device globals; no allocation) ----------------
__device__ float g_Gp[2][SPLITK][N * N];  // split-K partials (8 MB)
__device__ float g_Gs[N * N];
__device__ float g_Gt[N * N];
__device__ float g_n2s[N];       // diag of Gs (row squared norms)
__device__ float g_n2t[N];
__device__ float g_rowsum[2][N]; // per-row sums of G
__device__ float g_invm[2];      // 1/mean_sd, 1/mean_td
__device__ float g_pang[NFB];    // per-fused-block angle partials
__device__ float g_pdist[N];     // per-j distance-huber partials
__device__ float g_pcl[BH];      // per-row contrastive loss
__device__ unsigned int g_ctr1 = 0;  // reduce ticket
__device__ unsigned int g_ctr2 = 0;  // fused ticket

// symmetric tile map (bx <= by)
__device__ const int TBX[NTILE] = {0, 0, 0, 0, 1, 1, 1, 2, 2, 3};
__device__ const int TBY[NTILE] = {0, 1, 2, 3, 1, 2, 3, 2, 3, 3};

// ---------------- helpers ----------------
__device__ __forceinline__ const float* row_ptr(const float* q, const float* p, int r) {
    return (r < BH) ? (q + r * D) : (p + (r - BH) * D);
}

// block-wide sum, EXPLICIT linear tid/count; result broadcast to all threads.
__device__ __forceinline__ float block_sum_tid(float v, int tid, int nthreads) {
    __shared__ float sbuf[9];
    __syncthreads();                       // protect sbuf reuse across calls
    #pragma unroll
    for (int o = 16; o > 0; o >>= 1) v += __shfl_down_sync(0xffffffffu, v, o);
    int w = tid >> 5, l = tid & 31;
    if (l == 0) sbuf[w] = v;
    __syncthreads();
    if (tid == 0) {
        float s = 0.0f;
        int nw = nthreads >> 5;
        for (int i = 0; i < nw; i++) s += sbuf[i];
        sbuf[8] = s;
    }
    __syncthreads();
    return sbuf[8];
}

__device__ __forceinline__ float block_sum_all(float v) {
    return block_sum_tid(v, threadIdx.x, blockDim.x);
}

// block-wide max, result broadcast (1-D blocks only).
__device__ __forceinline__ float block_max_all(float v) {
    __shared__ float mbuf[9];
    __syncthreads();
    #pragma unroll
    for (int o = 16; o > 0; o >>= 1) v = fmaxf(v, __shfl_down_sync(0xffffffffu, v, o));
    int w = threadIdx.x >> 5, l = threadIdx.x & 31;
    if (l == 0) mbuf[w] = v;
    __syncthreads();
    if (threadIdx.x == 0) {
        float s = -INFINITY;
        int nw = blockDim.x >> 5;
        for (int i = 0; i < nw; i++) s = fmaxf(s, mbuf[i]);
        mbuf[8] = s;
    }
    __syncthreads();
    return mbuf[8];
}

// ---------------- K1: split-K Gram partials, symmetric tiles only ----------------
// grid (10, 32): x = tile (bx<=by); y = mat*16 + split. block = 256 threads.
// All 6 gmem float4 loads issued up-front (MLP=6, one latency exposure);
// double-buffered smem overlaps STS of stage s+1 with FFMA of stage s.
__global__ void __launch_bounds__(256) gram_kernel(
        const float* __restrict__ sq, const float* __restrict__ sp,
        const float* __restrict__ tq, const float* __restrict__ tp) {
    int mat = blockIdx.y >> 4;
    int split = blockIdx.y & 15;
    const float* q = mat ? tq : sq;
    const float* p = mat ? tp : sp;
    float* Gp = g_Gp[mat][split];

    __shared__ float As[2][TSTEP][68];   // k-major, double buffered
    __shared__ float Bs[2][TSTEP][68];

    int bx = TBX[blockIdx.x], by = TBY[blockIdx.x];
    int TI = bx * 64;
    int TK = by * 64;
    int tid = threadIdx.x;
    int tx = tid & 15, ty = tid >> 4;
    int lr = tid >> 2;
    int lc = (tid & 3) * 4;

    int k0 = split * CHUNK;
    const float* arow = row_ptr(q, p, TI + lr) + lc + k0;
    const float* brow = row_ptr(q, p, TK + lr) + lc + k0;

    // preload the whole chunk: 3 stages x (A,B) = 6 float4, MLP=6
    float4 av[NSTAGE], bv[NSTAGE];
    #pragma unroll
    for (int s = 0; s < NSTAGE; s++) {
        av[s] = *(const float4*)(arow + s * TSTEP);
        bv[s] = *(const float4*)(brow + s * TSTEP);
    }

    float acc[4][4];
    #pragma unroll
    for (int a = 0; a < 4; a++)
        #pragma unroll
        for (int b = 0; b < 4; b++) acc[a][b] = 0.0f;

    // stage 0 into buffer 0
    As[0][lc + 0][lr] = av[0].x; As[0][lc + 1][lr] = av[0].y;
    As[0][lc + 2][lr] = av[0].z; As[0][lc + 3][lr] = av[0].w;
    Bs[0][lc + 0][lr] = bv[0].x; Bs[0][lc + 1][lr] = bv[0].y;
    Bs[0][lc + 2][lr] = bv[0].z; Bs[0][lc + 3][lr] = bv[0].w;
    __syncthreads();

    #pragma unroll
    for (int s = 0; s < NSTAGE; s++) {
        int cur = s & 1;
        // STS next stage into the other buffer (overlaps with FFMA below)
        if (s + 1 < NSTAGE) {
            int nxt = (s + 1) & 1;
            As[nxt][lc + 0][lr] = av[s + 1].x; As[nxt][lc + 1][lr] = av[s + 1].y;
            As[nxt][lc + 2][lr] = av[s + 1].z; As[nxt][lc + 3][lr] = av[s + 1].w;
            Bs[nxt][lc + 0][lr] = bv[s + 1].x; Bs[nxt][lc + 1][lr] = bv[s + 1].y;
            Bs[nxt][lc + 2][lr] = bv[s + 1].z; Bs[nxt][lc + 3][lr] = bv[s + 1].w;
        }
        #pragma unroll
        for (int kk = 0; kk < TSTEP; kk++) {
            float4 a = *(const float4*)&As[cur][kk][ty * 4];
            float4 b = *(const float4*)&Bs[cur][kk][tx * 4];
            acc[0][0] = fmaf(a.x, b.x, acc[0][0]);
            acc[0][1] = fmaf(a.x, b.y, acc[0][1]);
            acc[0][2] = fmaf(a.x, b.z, acc[0][2]);
            acc[0][3] = fmaf(a.x, b.w, acc[0][3]);
            acc[1][0] = fmaf(a.y, b.x, acc[1][0]);
            acc[1][1] = fmaf(a.y, b.y, acc[1][1]);
            acc[1][2] = fmaf(a.y, b.z, acc[1][2]);
            acc[1][3] = fmaf(a.y, b.w, acc[1][3]);
            acc[2][0] = fmaf(a.z, b.x, acc[2][0]);
            acc[2][1] = fmaf(a.z, b.y, acc[2][1]);
            acc[2][2] = fmaf(a.z, b.z, acc[2][2]);
            acc[2][3] = fmaf(a.z, b.w, acc[2][3]);
            acc[3][0] = fmaf(a.w, b.x, acc[3][0]);
            acc[3][1] = fmaf(a.w, b.y, acc[3][1]);
            acc[3][2] = fmaf(a.w, b.z, acc[3][2]);
            acc[3][3] = fmaf(a.w, b.w, acc[3][3]);
        }
        __syncthreads();
    }

    // normal tile write: row TI+ty*4+r, cols TK+tx*4..+3
    #pragma unroll
    for (int r = 0; r < 4; r++) {
        float4 v = make_float4(acc[r][0], acc[r][1], acc[r][2], acc[r][3]);
        *(float4*)&Gp[(TI + ty * 4 + r) * N + TK + tx * 4] = v;
    }
    // transposed tile write for off-diagonal tiles
    if (bx != by) {
        #pragma unroll
        for (int c = 0; c < 4; c++) {
            float4 v = make_float4(acc[0][c], acc[1][c], acc[2][c], acc[3][c]);
            *(float4*)&Gp[(TK + tx * 4 + c) * N + TI + ty * 4] = v;
        }
    }
}

// ---------------- K2: fold split-K, diag + row sums; ticket block -> means ----------------
// grid (N, 2), block 256.
__global__ void __launch_bounds__(256) reduce_kernel() {
    int i = blockIdx.x, z = blockIdx.y, t = threadIdx.x;
    float s = 0.0f;
    #pragma unroll
    for (int pp = 0; pp < SPLITK; pp++) s += g_Gp[z][pp][i * N + t];
    (z ? g_Gt : g_Gs)[i * N + t] = s;
    if (t == i) (z ? g_n2t : g_n2s)[i] = s;
    float rsum = block_sum_all(s);
    if (t == 0) g_rowsum[z][i] = rsum;

    __shared__ unsigned int stick;
    __threadfence();
    if (t == 0) stick = atomicAdd(&g_ctr1, 1);
    __syncthreads();
    if (stick == 2 * N - 1) {
        // triu ds sum = N*tr(G) - sum(G)
        float tr_s  = block_sum_all(g_n2s[t]);
        float tr_t  = block_sum_all(g_n2t[t]);
        float sum_s = block_sum_all(g_rowsum[0][t]);
        float sum_t = block_sum_all(g_rowsum[1][t]);
        if (t == 0) {
            g_invm[0] = 1.0f / (((float)N * tr_s - sum_s) / CNT2 + EPSF);
            g_invm[1] = 1.0f / (((float)N * tr_t - sum_t) / CNT2 + EPSF);
            g_ctr1 = 0;   // reset for next graph replay
        }
    }
}

// ---------------- K3: fused angle + dist + contrastive; ticket block -> output ----------------
// grid 512: bid = jquad*8 + q. Block handles 4 j's (jbase..jbase+3), i-comb q (step 8).
// cos(i,k at vertex j) = r_jk * ( r_ji*(g_ik - g_jk) + p_i ),  p_i = (g_jj - g_ji)*r_ji
// r row diagonal zeroed => i==j, k==j terms exactly 0; (i,k) symmetric => i>k only.
__global__ void __launch_bounds__(256) fused_kernel(float* __restrict__ out, int out_size) {
    int bid = blockIdx.x;
    int jquad = bid >> 3;
    int q = bid & 7;
    int jbase = jquad * 4;
    int k = threadIdx.x;

    __shared__ float n2s_sh[N], n2t_sh[N];
    __shared__ float gsj_sh[4][N], gtj_sh[4][N];
    __shared__ float4 sp_sh[4][N];   // {rs, ps, rt, pt} per (jj, i)

    float n2sk = g_n2s[k], n2tk = g_n2t[k];
    n2s_sh[k] = n2sk; n2t_sh[k] = n2tk;
    float gsv[4], gtv[4];
    #pragma unroll
    for (int jj = 0; jj < 4; jj++) {
        gsv[jj] = g_Gs[(jbase + jj) * N + k];
        gtv[jj] = g_Gt[(jbase + jj) * N + k];
        gsj_sh[jj][k] = gsv[jj];
        gtj_sh[jj][k] = gtv[jj];
    }
    __syncthreads();

    float rsk[4], rtk[4];
    #pragma unroll
    for (int jj = 0; jj < 4; jj++) {
        int j = jbase + jj;
        float ds = n2s_sh[j] + n2sk - 2.0f * gsv[jj];
        float dt = n2t_sh[j] + n2tk - 2.0f * gtv[jj];
        float rs = (k == j) ? 0.0f : 1.0f / (sqrtf(fmaxf(ds, 0.0f)) + EPSF);
        float rt = (k == j) ? 0.0f : 1.0f / (sqrtf(fmaxf(dt, 0.0f)) + EPSF);
        rsk[jj] = rs; rtk[jj] = rt;
        sp_sh[jj][k] = make_float4(rs, (n2s_sh[j] - gsv[jj]) * rs,
                                   rt, (n2t_sh[j] - gtv[jj]) * rt);
    }
    __syncthreads();

    // ---- dist huber + contrastive for j = jbase + q (q < 4 only; block-uniform) ----
    if (q < 4) {
        int j = jbase + q;
        float gs = gsj_sh[q][k], gt = gtj_sh[q][k];
        float ds = n2s_sh[j] + n2sk - 2.0f * gs;
        float dt = n2t_sh[j] + n2tk - 2.0f * gt;
        float v = 0.0f;
        if (k > j) {
            float diff = ds * g_invm[0] - dt * g_invm[1];
            float a = fabsf(diff), m = fminf(a, 1.0f);
            v = 0.5f * m * (2.0f * a - m);
        }
        float sd = block_sum_all(v);
        if (k == 0) g_pdist[j] = sd;
        if (j < BH) {
            float sval = (k < BH) ? gsj_sh[q][BH + k] : -INFINITY;
            float mx = block_max_all(sval);
            float ex = (k < BH) ? expf(INV_TEMP * (sval - mx)) : 0.0f;
            float sm = block_sum_all(ex);
            if (k == 0)
                g_pcl[j] = INV_TEMP * mx + logf(sm) - INV_TEMP * gsj_sh[q][BH + j];
        }
    }

    // ---- angle loop: i > k (pair symmetry), comb q of 8, software-pipelined ----
    const float* __restrict__ Gsk = g_Gs + k;   // column k (stride N)
    const float* __restrict__ Gtk = g_Gt + k;
    int wbase = k & ~31;
    float acc = 0.0f;
    int i0 = wbase + 1 + q;
    if (i0 < N) {
        float gsik = Gsk[i0 * N];
        float gtik = Gtk[i0 * N];
        for (int i = i0; i < N; i += 8) {
            int inext = i + 8;
            float gs_n = 0.0f, gt_n = 0.0f;
            if (inext < N) {           // prefetch next iteration's columns
                gs_n = Gsk[inext * N];
                gt_n = Gtk[inext * N];
            }
            float pred = (i > k) ? 1.0f : 0.0f;
            float hsum = 0.0f;
            #pragma unroll
            for (int jj = 0; jj < 4; jj++) {
                float4 c = sp_sh[jj][i];
                float us = fmaf(c.x, gsik - gsv[jj], c.y);
                float ut = fmaf(c.z, gtik - gtv[jj], c.w);
                float d  = fmaf(rtk[jj], -ut, rsk[jj] * us);  // cos_s - cos_t
                float a  = fabsf(d);
                float m  = fminf(a, 1.0f);
                hsum += m * fmaf(2.0f, a, -m);                // 2*huber
            }
            acc = fmaf(pred, hsum, acc);
            gsik = gs_n; gtik = gt_n;
        }
    }
    // sum_{i>k} 2*huber == sum_{i!=k} huber
    float sa = block_sum_all(acc);
    if (k == 0) g_pang[bid] = sa;

    // ---- ticket: last block combines everything and writes output ----
    __shared__ unsigned int stick;
    __threadfence();
    if (k == 0) stick = atomicAdd(&g_ctr2, 1);
    __syncthreads();
    if (stick == NFB - 1) {
        __threadfence();
        float dsum  = block_sum_all(g_pdist[k]);
        float asum  = block_sum_all(g_pang[k] + g_pang[k + 256]);
        float clsum = block_sum_all((k < BH) ? g_pcl[k] : 0.0f);
        if (k == 0) {
            float contrastive = clsum / (float)BH;
            float kd = 0.5f * (dsum / CNT2) + 0.5f * (asum / CNT3);
            if (out_size > 0) out[0] = contrastive + kd;
            if (out_size > 1) out[1] = contrastive;
            if (out_size > 2) out[2] = kd;
            g_ctr2 = 0;   // reset for next graph replay
        }
    }
}

// ---------------- launch ----------------
extern "C" void kernel_launch(void* const* d_in, const int* in_sizes, int n_in,
                              void* d_out, int out_size) {
    const float* sq = (const float*)d_in[0];
    const float* sp = (const float*)d_in[1];
    const float* tq = (const float*)d_in[2];
    const float* tp = (const float*)d_in[3];
    float* out = (float*)d_out;

    gram_kernel<<<dim3(NTILE, 32), 256>>>(sq, sp, tq, tp);
    reduce_kernel<<<dim3(N, 2), 256>>>();
    fused_kernel<<<NFB, 256>>>(out, out_size);
}

// round 14
// speedup vs baseline: 1.4495x; 1.4495x over previous
#include <cuda_runtime.h>
#include <math.h>

#define N 256            // 2B
#define BH 128           // B
#define D 768
#define EPSF 1e-8f
#define INV_TEMP 20.0f   // 1/0.05
#define CNT2 32640.0f    // N(N-1)/2
#define CNT3 16581120.0f // N(N-1)(N-2)

#define SPLITK 16
#define CHUNK 48         // D / SPLITK
#define TSTEP 16         // k per smem stage
#define NSTAGE (CHUNK / TSTEP)   // 3

#define NTILE 10         // symmetric 4x4 -> 10 tiles (bx <= by)
#define NFB 512          // fused grid: 64 j-quads x 8 i-combs

typedef unsigned long long u64t;

// ---------------- scratch (device globals; no allocation) ----------------
__device__ float g_Gp[2][SPLITK][N * N];  // split-K partials (8 MB)
__device__ float g_Gs[N * N];
__device__ float g_Gt[N * N];
__device__ float g_n2s[N];       // diag of Gs (row squared norms)
__device__ float g_n2t[N];
__device__ float g_rowsum[2][N]; // per-row sums of G
__device__ float g_invm[2];      // 1/mean_sd, 1/mean_td
__device__ float g_pang[NFB];    // per-fused-block angle partials
__device__ float g_pdist[N];     // per-j distance-huber partials
__device__ float g_pcl[BH];      // per-row contrastive loss
__device__ unsigned int g_ctr1 = 0;  // reduce ticket
__device__ unsigned int g_ctr2 = 0;  // fused ticket

// symmetric tile map (bx <= by)
__device__ const int TBX[NTILE] = {0, 0, 0, 0, 1, 1, 1, 2, 2, 3};
__device__ const int TBY[NTILE] = {0, 1, 2, 3, 1, 2, 3, 2, 3, 3};

// ---------------- f32x2 packed helpers (sm_103a FFMA2 path) ----------------
__device__ __forceinline__ u64t pack2(float lo, float hi) {
    u64t r; asm("mov.b64 %0, {%1, %2};" : "=l"(r) : "f"(lo), "f"(hi)); return r;
}
__device__ __forceinline__ void unpack2(float& lo, float& hi, u64t v) {
    asm("mov.b64 {%0, %1}, %2;" : "=f"(lo), "=f"(hi) : "l"(v));
}
__device__ __forceinline__ void fma2(u64t& d, u64t a, u64t b) {
    asm("fma.rn.f32x2 %0, %1, %2, %0;" : "+l"(d) : "l"(a), "l"(b));
}

// ---------------- helpers ----------------
__device__ __forceinline__ const float* row_ptr(const float* q, const float* p, int r) {
    return (r < BH) ? (q + r * D) : (p + (r - BH) * D);
}

// block-wide sum, EXPLICIT linear tid/count; result broadcast to all threads.
__device__ __forceinline__ float block_sum_tid(float v, int tid, int nthreads) {
    __shared__ float sbuf[9];
    __syncthreads();                       // protect sbuf reuse across calls
    #pragma unroll
    for (int o = 16; o > 0; o >>= 1) v += __shfl_down_sync(0xffffffffu, v, o);
    int w = tid >> 5, l = tid & 31;
    if (l == 0) sbuf[w] = v;
    __syncthreads();
    if (tid == 0) {
        float s = 0.0f;
        int nw = nthreads >> 5;
        for (int i = 0; i < nw; i++) s += sbuf[i];
        sbuf[8] = s;
    }
    __syncthreads();
    return sbuf[8];
}

__device__ __forceinline__ float block_sum_all(float v) {
    return block_sum_tid(v, threadIdx.x, blockDim.x);
}

// block-wide max, result broadcast (1-D blocks only).
__device__ __forceinline__ float block_max_all(float v) {
    __shared__ float mbuf[9];
    __syncthreads();
    #pragma unroll
    for (int o = 16; o > 0; o >>= 1) v = fmaxf(v, __shfl_down_sync(0xffffffffu, v, o));
    int w = threadIdx.x >> 5, l = threadIdx.x & 31;
    if (l == 0) mbuf[w] = v;
    __syncthreads();
    if (threadIdx.x == 0) {
        float s = -INFINITY;
        int nw = blockDim.x >> 5;
        for (int i = 0; i < nw; i++) s = fmaxf(s, mbuf[i]);
        mbuf[8] = s;
    }
    __syncthreads();
    return mbuf[8];
}

// ---------------- K1: split-K Gram partials, symmetric tiles, FFMA2 inner loop ----------------
// grid (10, 32): x = tile (bx<=by); y = mat*16 + split. block = 256 threads.
// Off-diagonal tiles are written twice (normal + register-transposed).
__global__ void __launch_bounds__(256) gram_kernel(
        const float* __restrict__ sq, const float* __restrict__ sp,
        const float* __restrict__ tq, const float* __restrict__ tp) {
    int mat = blockIdx.y >> 4;
    int split = blockIdx.y & 15;
    const float* q = mat ? tq : sq;
    const float* p = mat ? tp : sp;
    float* Gp = g_Gp[mat][split];

    __shared__ float As[TSTEP][68];   // k-major
    __shared__ float Bs[TSTEP][68];

    int bx = TBX[blockIdx.x], by = TBY[blockIdx.x];
    int TI = bx * 64;
    int TK = by * 64;
    int tid = threadIdx.x;
    int tx = tid & 15, ty = tid >> 4;
    int lr = tid >> 2;
    int lc = (tid & 3) * 4;

    // packed accumulators: acc01[r] = {acc[r][0], acc[r][1]}, acc23[r] = {acc[r][2], acc[r][3]}
    u64t acc01[4] = {0ull, 0ull, 0ull, 0ull};
    u64t acc23[4] = {0ull, 0ull, 0ull, 0ull};

    int k0base = split * CHUNK;
    const float* arow = row_ptr(q, p, TI + lr) + lc;
    const float* brow = row_ptr(q, p, TK + lr) + lc;

    float4 av = *(const float4*)(arow + k0base);
    float4 bv = *(const float4*)(brow + k0base);

    #pragma unroll
    for (int s = 0; s < NSTAGE; s++) {
        As[lc + 0][lr] = av.x; As[lc + 1][lr] = av.y;
        As[lc + 2][lr] = av.z; As[lc + 3][lr] = av.w;
        Bs[lc + 0][lr] = bv.x; Bs[lc + 1][lr] = bv.y;
        Bs[lc + 2][lr] = bv.z; Bs[lc + 3][lr] = bv.w;
        __syncthreads();
        // prefetch next stage while computing this one
        if (s + 1 < NSTAGE) {
            av = *(const float4*)(arow + k0base + (s + 1) * TSTEP);
            bv = *(const float4*)(brow + k0base + (s + 1) * TSTEP);
        }
        #pragma unroll
        for (int kk = 0; kk < TSTEP; kk++) {
            float4 a = *(const float4*)&As[kk][ty * 4];
            float4 b = *(const float4*)&Bs[kk][tx * 4];
            u64t bxy = pack2(b.x, b.y);
            u64t bzw = pack2(b.z, b.w);
            u64t a0 = pack2(a.x, a.x);
            u64t a1 = pack2(a.y, a.y);
            u64t a2 = pack2(a.z, a.z);
            u64t a3 = pack2(a.w, a.w);
            fma2(acc01[0], a0, bxy); fma2(acc23[0], a0, bzw);
            fma2(acc01[1], a1, bxy); fma2(acc23[1], a1, bzw);
            fma2(acc01[2], a2, bxy); fma2(acc23[2], a2, bzw);
            fma2(acc01[3], a3, bxy); fma2(acc23[3], a3, bzw);
        }
        __syncthreads();
    }

    float acc[4][4];
    #pragma unroll
    for (int r = 0; r < 4; r++) {
        unpack2(acc[r][0], acc[r][1], acc01[r]);
        unpack2(acc[r][2], acc[r][3], acc23[r]);
    }

    // normal tile write: row TI+ty*4+r, cols TK+tx*4..+3
    #pragma unroll
    for (int r = 0; r < 4; r++) {
        float4 v = make_float4(acc[r][0], acc[r][1], acc[r][2], acc[r][3]);
        *(float4*)&Gp[(TI + ty * 4 + r) * N + TK + tx * 4] = v;
    }
    // transposed tile write for off-diagonal tiles:
    // G[TK+tx*4+c][TI+ty*4+r] = acc[r][c] -> contiguous float4 over r
    if (bx != by) {
        #pragma unroll
        for (int c = 0; c < 4; c++) {
            float4 v = make_float4(acc[0][c], acc[1][c], acc[2][c], acc[3][c]);
            *(float4*)&Gp[(TK + tx * 4 + c) * N + TI + ty * 4] = v;
        }
    }
}

// ---------------- K2: fold split-K, diag + row sums; ticket block -> means ----------------
// grid (N, 2), block 256.
__global__ void __launch_bounds__(256) reduce_kernel() {
    int i = blockIdx.x, z = blockIdx.y, t = threadIdx.x;
    float s = 0.0f;
    #pragma unroll
    for (int pp = 0; pp < SPLITK; pp++) s += g_Gp[z][pp][i * N + t];
    (z ? g_Gt : g_Gs)[i * N + t] = s;
    if (t == i) (z ? g_n2t : g_n2s)[i] = s;
    float rsum = block_sum_all(s);
    if (t == 0) g_rowsum[z][i] = rsum;

    __shared__ unsigned int stick;
    __threadfence();
    if (t == 0) stick = atomicAdd(&g_ctr1, 1);
    __syncthreads();
    if (stick == 2 * N - 1) {
        // triu ds sum = N*tr(G) - sum(G)
        float tr_s  = block_sum_all(g_n2s[t]);
        float tr_t  = block_sum_all(g_n2t[t]);
        float sum_s = block_sum_all(g_rowsum[0][t]);
        float sum_t = block_sum_all(g_rowsum[1][t]);
        if (t == 0) {
            g_invm[0] = 1.0f / (((float)N * tr_s - sum_s) / CNT2 + EPSF);
            g_invm[1] = 1.0f / (((float)N * tr_t - sum_t) / CNT2 + EPSF);
            g_ctr1 = 0;   // reset for next graph replay
        }
    }
}

// ---------------- K3: fused angle + dist + contrastive; ticket block -> output ----------------
// grid 512: bid = jquad*8 + q. Block handles 4 j's (jbase..jbase+3), i-comb q (step 8).
// cos(i,k at vertex j) = r_jk * ( r_ji*(g_ik - g_jk) + p_i ),  p_i = (g_jj - g_ji)*r_ji
// r row diagonal zeroed => i==j, k==j terms exactly 0; (i,k) symmetric => i>k only.
__global__ void __launch_bounds__(256) fused_kernel(float* __restrict__ out, int out_size) {
    int bid = blockIdx.x;
    int jquad = bid >> 3;
    int q = bid & 7;
    int jbase = jquad * 4;
    int k = threadIdx.x;

    __shared__ float n2s_sh[N], n2t_sh[N];
    __shared__ float gsj_sh[4][N], gtj_sh[4][N];
    __shared__ float4 sp_sh[4][N];   // {rs, ps, rt, pt} per (jj, i)

    float n2sk = g_n2s[k], n2tk = g_n2t[k];
    n2s_sh[k] = n2sk; n2t_sh[k] = n2tk;
    float gsv[4], gtv[4];
    #pragma unroll
    for (int jj = 0; jj < 4; jj++) {
        gsv[jj] = g_Gs[(jbase + jj) * N + k];
        gtv[jj] = g_Gt[(jbase + jj) * N + k];
        gsj_sh[jj][k] = gsv[jj];
        gtj_sh[jj][k] = gtv[jj];
    }
    __syncthreads();

    float rsk[4], rtk[4];
    #pragma unroll
    for (int jj = 0; jj < 4; jj++) {
        int j = jbase + jj;
        float ds = n2s_sh[j] + n2sk - 2.0f * gsv[jj];
        float dt = n2t_sh[j] + n2tk - 2.0f * gtv[jj];
        float rs = (k == j) ? 0.0f : 1.0f / (sqrtf(fmaxf(ds, 0.0f)) + EPSF);
        float rt = (k == j) ? 0.0f : 1.0f / (sqrtf(fmaxf(dt, 0.0f)) + EPSF);
        rsk[jj] = rs; rtk[jj] = rt;
        sp_sh[jj][k] = make_float4(rs, (n2s_sh[j] - gsv[jj]) * rs,
                                   rt, (n2t_sh[j] - gtv[jj]) * rt);
    }
    __syncthreads();

    // ---- dist huber + contrastive for j = jbase + q (q < 4 only; block-uniform) ----
    if (q < 4) {
        int j = jbase + q;
        float gs = gsj_sh[q][k], gt = gtj_sh[q][k];
        float ds = n2s_sh[j] + n2sk - 2.0f * gs;
        float dt = n2t_sh[j] + n2tk - 2.0f * gt;
        float v = 0.0f;
        if (k > j) {
            float diff = ds * g_invm[0] - dt * g_invm[1];
            float a = fabsf(diff), m = fminf(a, 1.0f);
            v = 0.5f * m * (2.0f * a - m);
        }
        float sd = block_sum_all(v);
        if (k == 0) g_pdist[j] = sd;
        if (j < BH) {
            float sval = (k < BH) ? gsj_sh[q][BH + k] : -INFINITY;
            float mx = block_max_all(sval);
            float ex = (k < BH) ? expf(INV_TEMP * (sval - mx)) : 0.0f;
            float sm = block_sum_all(ex);
            if (k == 0)
                g_pcl[j] = INV_TEMP * mx + logf(sm) - INV_TEMP * gsj_sh[q][BH + j];
        }
    }

    // ---- angle loop: i > k (pair symmetry), comb q of 8, warp-uniform base ----
    const float* __restrict__ Gsk = g_Gs + k;   // column k (stride N)
    const float* __restrict__ Gtk = g_Gt + k;
    int wbase = k & ~31;
    float acc = 0.0f;
    #pragma unroll 4
    for (int i = wbase + 1 + q; i < N; i += 8) {
        float gsik = Gsk[i * N];
        float gtik = Gtk[i * N];
        float pred = (i > k) ? 1.0f : 0.0f;
        float hsum = 0.0f;
        #pragma unroll
        for (int jj = 0; jj < 4; jj++) {
            float4 c = sp_sh[jj][i];
            float us = fmaf(c.x, gsik - gsv[jj], c.y);
            float ut = fmaf(c.z, gtik - gtv[jj], c.w);
            float d  = fmaf(rtk[jj], -ut, rsk[jj] * us);  // cos_s - cos_t
            float a  = fabsf(d);
            float m  = fminf(a, 1.0f);
            hsum += m * fmaf(2.0f, a, -m);                // 2*huber
        }
        acc = fmaf(pred, hsum, acc);
    }
    // sum_{i>k} 2*huber == sum_{i!=k} huber
    float sa = block_sum_all(acc);
    if (k == 0) g_pang[bid] = sa;

    // ---- ticket: last block combines everything and writes output ----
    __shared__ unsigned int stick;
    __threadfence();
    if (k == 0) stick = atomicAdd(&g_ctr2, 1);
    __syncthreads();
    if (stick == NFB - 1) {
        __threadfence();
        float dsum  = block_sum_all(g_pdist[k]);
        float asum  = block_sum_all(g_pang[k] + g_pang[k + 256]);
        float clsum = block_sum_all((k < BH) ? g_pcl[k] : 0.0f);
        if (k == 0) {
            float contrastive = clsum / (float)BH;
            float kd = 0.5f * (dsum / CNT2) + 0.5f * (asum / CNT3);
            if (out_size > 0) out[0] = contrastive + kd;
            if (out_size > 1) out[1] = contrastive;
            if (out_size > 2) out[2] = kd;
            g_ctr2 = 0;   // reset for next graph replay
        }
    }
}

// ---------------- launch ----------------
extern "C" void kernel_launch(void* const* d_in, const int* in_sizes, int n_in,
                              void* d_out, int out_size) {
    const float* sq = (const float*)d_in[0];
    const float* sp = (const float*)d_in[1];
    const float* tq = (const float*)d_in[2];
    const float* tp = (const float*)d_in[3];
    float* out = (float*)d_out;

    gram_kernel<<<dim3(NTILE, 32), 256>>>(sq, sp, tq, tp);
    reduce_kernel<<<dim3(N, 2), 256>>>();
    fused_kernel<<<NFB, 256>>>(out, out_size);
}

// round 16
// speedup vs baseline: 1.5778x; 1.0885x over previous
#include <cuda_runtime.h>
#include <math.h>

#define N 256            // 2B
#define BH 128           // B
#define D 768
#define EPSF 1e-8f
#define INV_TEMP 20.0f   // 1/0.05
#define CNT2 32640.0f    // N(N-1)/2
#define CNT3 16581120.0f // N(N-1)(N-2)

#define SPLITK 16
#define CHUNK 48         // D / SPLITK
#define TSTEP 16         // k per smem stage
#define NSTAGE (CHUNK / TSTEP)   // 3

#define NTILE 10         // symmetric 4x4 -> 10 tiles (bx <= by)
#define JT 8             // j's per fused block
#define NFB 256          // fused grid: 32 j-octs x 8 i-combs

// ---------------- scratch (device globals; no allocation) ----------------
__device__ float g_Gp[2][SPLITK][N * N];  // split-K partials (8 MB)
__device__ float g_Gs[N * N];
__device__ float g_Gt[N * N];
__device__ float g_n2s[N];       // diag of Gs (row squared norms)
__device__ float g_n2t[N];
__device__ float g_rowsum[2][N]; // per-row sums of G
__device__ float g_invm[2];      // 1/mean_sd, 1/mean_td
__device__ float g_pang[NFB];    // per-fused-block angle partials
__device__ float g_pdist[N];     // per-j distance-huber partials
__device__ float g_pcl[BH];      // per-row contrastive loss
__device__ unsigned int g_ctr1 = 0;  // reduce ticket
__device__ unsigned int g_ctr2 = 0;  // fused ticket

// symmetric tile map (bx <= by)
__device__ const int TBX[NTILE] = {0, 0, 0, 0, 1, 1, 1, 2, 2, 3};
__device__ const int TBY[NTILE] = {0, 1, 2, 3, 1, 2, 3, 2, 3, 3};

// ---------------- helpers ----------------
__device__ __forceinline__ const float* row_ptr(const float* q, const float* p, int r) {
    return (r < BH) ? (q + r * D) : (p + (r - BH) * D);
}

// block-wide sum, EXPLICIT linear tid/count; result broadcast to all threads.
__device__ __forceinline__ float block_sum_tid(float v, int tid, int nthreads) {
    __shared__ float sbuf[9];
    __syncthreads();                       // protect sbuf reuse across calls
    #pragma unroll
    for (int o = 16; o > 0; o >>= 1) v += __shfl_down_sync(0xffffffffu, v, o);
    int w = tid >> 5, l = tid & 31;
    if (l == 0) sbuf[w] = v;
    __syncthreads();
    if (tid == 0) {
        float s = 0.0f;
        int nw = nthreads >> 5;
        for (int i = 0; i < nw; i++) s += sbuf[i];
        sbuf[8] = s;
    }
    __syncthreads();
    return sbuf[8];
}

__device__ __forceinline__ float block_sum_all(float v) {
    return block_sum_tid(v, threadIdx.x, blockDim.x);
}

// block-wide max, result broadcast (1-D blocks only).
__device__ __forceinline__ float block_max_all(float v) {
    __shared__ float mbuf[9];
    __syncthreads();
    #pragma unroll
    for (int o = 16; o > 0; o >>= 1) v = fmaxf(v, __shfl_down_sync(0xffffffffu, v, o));
    int w = threadIdx.x >> 5, l = threadIdx.x & 31;
    if (l == 0) mbuf[w] = v;
    __syncthreads();
    if (threadIdx.x == 0) {
        float s = -INFINITY;
        int nw = blockDim.x >> 5;
        for (int i = 0; i < nw; i++) s = fmaxf(s, mbuf[i]);
        mbuf[8] = s;
    }
    __syncthreads();
    return mbuf[8];
}

// ---------------- K1: split-K Gram partials, symmetric tiles only (R12 scalar) ----------------
// grid (10, 32): x = tile (bx<=by); y = mat*16 + split. block = 256 threads.
__global__ void __launch_bounds__(256) gram_kernel(
        const float* __restrict__ sq, const float* __restrict__ sp,
        const float* __restrict__ tq, const float* __restrict__ tp) {
    int mat = blockIdx.y >> 4;
    int split = blockIdx.y & 15;
    const float* q = mat ? tq : sq;
    const float* p = mat ? tp : sp;
    float* Gp = g_Gp[mat][split];

    __shared__ float As[TSTEP][68];   // k-major
    __shared__ float Bs[TSTEP][68];

    int bx = TBX[blockIdx.x], by = TBY[blockIdx.x];
    int TI = bx * 64;
    int TK = by * 64;
    int tid = threadIdx.x;
    int tx = tid & 15, ty = tid >> 4;
    int lr = tid >> 2;
    int lc = (tid & 3) * 4;

    float acc[4][4];
    #pragma unroll
    for (int a = 0; a < 4; a++)
        #pragma unroll
        for (int b = 0; b < 4; b++) acc[a][b] = 0.0f;

    int k0base = split * CHUNK;
    const float* arow = row_ptr(q, p, TI + lr) + lc;
    const float* brow = row_ptr(q, p, TK + lr) + lc;

    float4 av = *(const float4*)(arow + k0base);
    float4 bv = *(const float4*)(brow + k0base);

    #pragma unroll
    for (int s = 0; s < NSTAGE; s++) {
        As[lc + 0][lr] = av.x; As[lc + 1][lr] = av.y;
        As[lc + 2][lr] = av.z; As[lc + 3][lr] = av.w;
        Bs[lc + 0][lr] = bv.x; Bs[lc + 1][lr] = bv.y;
        Bs[lc + 2][lr] = bv.z; Bs[lc + 3][lr] = bv.w;
        __syncthreads();
        if (s + 1 < NSTAGE) {
            av = *(const float4*)(arow + k0base + (s + 1) * TSTEP);
            bv = *(const float4*)(brow + k0base + (s + 1) * TSTEP);
        }
        #pragma unroll
        for (int kk = 0; kk < TSTEP; kk++) {
            float4 a = *(const float4*)&As[kk][ty * 4];
            float4 b = *(const float4*)&Bs[kk][tx * 4];
            acc[0][0] = fmaf(a.x, b.x, acc[0][0]);
            acc[0][1] = fmaf(a.x, b.y, acc[0][1]);
            acc[0][2] = fmaf(a.x, b.z, acc[0][2]);
            acc[0][3] = fmaf(a.x, b.w, acc[0][3]);
            acc[1][0] = fmaf(a.y, b.x, acc[1][0]);
            acc[1][1] = fmaf(a.y, b.y, acc[1][1]);
            acc[1][2] = fmaf(a.y, b.z, acc[1][2]);
            acc[1][3] = fmaf(a.y, b.w, acc[1][3]);
            acc[2][0] = fmaf(a.z, b.x, acc[2][0]);
            acc[2][1] = fmaf(a.z, b.y, acc[2][1]);
            acc[2][2] = fmaf(a.z, b.z, acc[2][2]);
            acc[2][3] = fmaf(a.z, b.w, acc[2][3]);
            acc[3][0] = fmaf(a.w, b.x, acc[3][0]);
            acc[3][1] = fmaf(a.w, b.y, acc[3][1]);
            acc[3][2] = fmaf(a.w, b.z, acc[3][2]);
            acc[3][3] = fmaf(a.w, b.w, acc[3][3]);
        }
        __syncthreads();
    }

    #pragma unroll
    for (int r = 0; r < 4; r++) {
        float4 v = make_float4(acc[r][0], acc[r][1], acc[r][2], acc[r][3]);
        *(float4*)&Gp[(TI + ty * 4 + r) * N + TK + tx * 4] = v;
    }
    if (bx != by) {
        #pragma unroll
        for (int c = 0; c < 4; c++) {
            float4 v = make_float4(acc[0][c], acc[1][c], acc[2][c], acc[3][c]);
            *(float4*)&Gp[(TK + tx * 4 + c) * N + TI + ty * 4] = v;
        }
    }
}

// ---------------- K2: fold split-K (float4), diag + row sums; ticket -> means ----------------
// grid (N, 2), block 64: thread t handles cols 4t..4t+3 of row i (float4, MLP=16).
__global__ void __launch_bounds__(64) reduce_kernel() {
    int i = blockIdx.x, z = blockIdx.y, t = threadIdx.x;
    float4 s = make_float4(0.f, 0.f, 0.f, 0.f);
    #pragma unroll
    for (int pp = 0; pp < SPLITK; pp++) {
        float4 v = *(const float4*)(g_Gp[z][pp] + i * N + 4 * t);
        s.x += v.x; s.y += v.y; s.z += v.z; s.w += v.w;
    }
    *(float4*)((z ? g_Gt : g_Gs) + i * N + 4 * t) = s;
    if ((i >> 2) == t) {
        int c = i & 3;
        float d = (c == 0) ? s.x : (c == 1) ? s.y : (c == 2) ? s.z : s.w;
        (z ? g_n2t : g_n2s)[i] = d;
    }
    float rsum = block_sum_tid(s.x + s.y + s.z + s.w, t, 64);
    if (t == 0) g_rowsum[z][i] = rsum;

    __shared__ unsigned int stick;
    __threadfence();
    if (t == 0) stick = atomicAdd(&g_ctr1, 1);
    __syncthreads();
    if (stick == 2 * N - 1) {
        float a = 0.f, b = 0.f, c = 0.f, d = 0.f;
        for (int u = t; u < N; u += 64) {
            a += g_n2s[u];       b += g_n2t[u];
            c += g_rowsum[0][u]; d += g_rowsum[1][u];
        }
        float tr_s  = block_sum_tid(a, t, 64);
        float tr_t  = block_sum_tid(b, t, 64);
        float sum_s = block_sum_tid(c, t, 64);
        float sum_t = block_sum_tid(d, t, 64);
        if (t == 0) {
            g_invm[0] = 1.0f / (((float)N * tr_s - sum_s) / CNT2 + EPSF);
            g_invm[1] = 1.0f / (((float)N * tr_t - sum_t) / CNT2 + EPSF);
            g_ctr1 = 0;   // reset for next graph replay
        }
    }
}

// ---------------- K3: fused angle + dist + contrastive; ticket block -> output ----------------
// grid 256: bid = joct*8 + q. Block handles 8 j's (jbase..jbase+7), i-comb q (step 8).
// cos(i,k at vertex j) = r_jk * ( r_ji*(g_ik - g_jk) + p_i ),  p_i = (g_jj - g_ji)*r_ji
// r row diagonal zeroed => i==j, k==j terms exactly 0; (i,k) symmetric => i>k only.
__global__ void __launch_bounds__(256) fused_kernel(float* __restrict__ out, int out_size) {
    int bid = blockIdx.x;
    int joct = bid >> 3;
    int q = bid & 7;
    int jbase = joct * JT;
    int k = threadIdx.x;

    __shared__ float n2s_sh[N], n2t_sh[N];
    __shared__ float gsh[JT][BH];    // student Gs[jbase+jj][BH + c] (contrastive slice)
    __shared__ float4 sp_sh[JT][N];  // {rs, ps, rt, pt} per (jj, i)   -> 32 KB

    float n2sk = g_n2s[k], n2tk = g_n2t[k];
    n2s_sh[k] = n2sk; n2t_sh[k] = n2tk;
    float gsv[JT], gtv[JT];
    #pragma unroll
    for (int jj = 0; jj < JT; jj++) {
        gsv[jj] = g_Gs[(jbase + jj) * N + k];
        gtv[jj] = g_Gt[(jbase + jj) * N + k];
        if (k >= BH) gsh[jj][k - BH] = gsv[jj];
    }
    __syncthreads();

    float rsk[JT], rtk[JT];
    #pragma unroll
    for (int jj = 0; jj < JT; jj++) {
        int j = jbase + jj;
        float ds = n2s_sh[j] + n2sk - 2.0f * gsv[jj];
        float dt = n2t_sh[j] + n2tk - 2.0f * gtv[jj];
        float rs = (k == j) ? 0.0f : 1.0f / (sqrtf(fmaxf(ds, 0.0f)) + EPSF);
        float rt = (k == j) ? 0.0f : 1.0f / (sqrtf(fmaxf(dt, 0.0f)) + EPSF);
        rsk[jj] = rs; rtk[jj] = rt;
        sp_sh[jj][k] = make_float4(rs, (n2s_sh[j] - gsv[jj]) * rs,
                                   rt, (n2t_sh[j] - gtv[jj]) * rt);
    }
    __syncthreads();

    // ---- dist huber + contrastive for j = jbase + q (every block, distinct j) ----
    {
        int j = jbase + q;
        float ds = n2s_sh[j] + n2sk - 2.0f * gsv[q];
        float dt = n2t_sh[j] + n2tk - 2.0f * gtv[q];
        float v = 0.0f;
        if (k > j) {
            float diff = ds * g_invm[0] - dt * g_invm[1];
            float a = fabsf(diff), m = fminf(a, 1.0f);
            v = 0.5f * m * (2.0f * a - m);
        }
        float sd = block_sum_all(v);
        if (k == 0) g_pdist[j] = sd;
        if (j < BH) {
            float sval = (k < BH) ? gsh[q][k] : -INFINITY;
            float mx = block_max_all(sval);
            float ex = (k < BH) ? expf(INV_TEMP * (sval - mx)) : 0.0f;
            float sm = block_sum_all(ex);
            if (k == 0)
                g_pcl[j] = INV_TEMP * mx + logf(sm) - INV_TEMP * gsh[q][j];
        }
    }

    // ---- angle loop: i > k (pair symmetry), comb q of 8, warp-uniform base ----
    const float* __restrict__ Gsk = g_Gs + k;   // column k (stride N)
    const float* __restrict__ Gtk = g_Gt + k;
    int wbase = k & ~31;
    float acc = 0.0f;
    #pragma unroll 2
    for (int i = wbase + 1 + q; i < N; i += 8) {
        float gsik = Gsk[i * N];
        float gtik = Gtk[i * N];
        float pred = (i > k) ? 1.0f : 0.0f;
        float hsum = 0.0f;
        #pragma unroll
        for (int jj = 0; jj < JT; jj++) {
            float4 c = sp_sh[jj][i];
            float us = fmaf(c.x, gsik - gsv[jj], c.y);
            float ut = fmaf(c.z, gtik - gtv[jj], c.w);
            float d  = fmaf(rtk[jj], -ut, rsk[jj] * us);  // cos_s - cos_t
            float a  = fabsf(d);
            float m  = fminf(a, 1.0f);
            hsum += m * fmaf(2.0f, a, -m);                // 2*huber
        }
        acc = fmaf(pred, hsum, acc);
    }
    // sum_{i>k} 2*huber == sum_{i!=k} huber
    float sa = block_sum_all(acc);
    if (k == 0) g_pang[bid] = sa;

    // ---- ticket: last block combines everything and writes output ----
    __shared__ unsigned int stick;
    __threadfence();
    if (k == 0) stick = atomicAdd(&g_ctr2, 1);
    __syncthreads();
    if (stick == NFB - 1) {
        __threadfence();
        float dsum  = block_sum_all(g_pdist[k]);
        float asum  = block_sum_all(g_pang[k]);
        float clsum = block_sum_all((k < BH) ? g_pcl[k] : 0.0f);
        if (k == 0) {
            float contrastive = clsum / (float)BH;
            float kd = 0.5f * (dsum / CNT2) + 0.5f * (asum / CNT3);
            if (out_size > 0) out[0] = contrastive + kd;
            if (out_size > 1) out[1] = contrastive;
            if (out_size > 2) out[2] = kd;
            g_ctr2 = 0;   // reset for next graph replay
        }
    }
}

// ---------------- launch ----------------
extern "C" void kernel_launch(void* const* d_in, const int* in_sizes, int n_in,
                              void* d_out, int out_size) {
    const float* sq = (const float*)d_in[0];
    const float* sp = (const float*)d_in[1];
    const float* tq = (const float*)d_in[2];
    const float* tp = (const float*)d_in[3];
    float* out = (float*)d_out;

    gram_kernel<<<dim3(NTILE, 32), 256>>>(sq, sp, tq, tp);
    reduce_kernel<<<dim3(N, 2), 64>>>();
    fused_kernel<<<NFB, 256>>>(out, out_size);
}

// round 17
// speedup vs baseline: 1.6089x; 1.0197x over previous
#include <cuda_runtime.h>
#include <math.h>

#define N 256            // 2B
#define BH 128           // B
#define D 768
#define EPSF 1e-8f
#define INV_TEMP 20.0f   // 1/0.05
#define CNT2 32640.0f    // N(N-1)/2
#define CNT3 16581120.0f // N(N-1)(N-2)

#define SPLITK 16
#define CHUNK 48         // D / SPLITK
#define TSTEP 16         // k per smem stage
#define NSTAGE (CHUNK / TSTEP)   // 3

#define NTILE 10         // symmetric 4x4 -> 10 tiles (bx <= by)
#define NTASKS (NTILE * 32)      // 320 gram tasks
#define JT 8             // j's per fused block
#define NB 256           // grid size (co-resident: 2/SM * 148 = 296 >= 256)

// ---------------- scratch (device globals; no allocation) ----------------
__device__ float g_Gp[2][SPLITK][N * N];  // split-K partials (8 MB)
__device__ float g_Gs[N * N];
__device__ float g_Gt[N * N];
__device__ float g_n2s[N];       // diag of Gs (row squared norms)
__device__ float g_n2t[N];
__device__ float g_rowsum[2][N]; // per-row sums of G
__device__ float g_pang[NB];     // per-block angle partials
__device__ float g_pdist[N];     // per-j distance-huber partials
__device__ float g_pcl[BH];      // per-row contrastive loss
__device__ unsigned int g_gbar[2];   // monotonic grid barriers (never reset)
__device__ unsigned int g_ctr2 = 0;  // final ticket (reset by winner)

// symmetric tile map (bx <= by)
__device__ const int TBX[NTILE] = {0, 0, 0, 0, 1, 1, 1, 2, 2, 3};
__device__ const int TBY[NTILE] = {0, 1, 2, 3, 1, 2, 3, 2, 3, 3};

// ---------------- shared memory union (phases don't overlap) ----------------
union SmemU {
    struct { float As[TSTEP][68]; float Bs[TSTEP][68]; } g;           // ~8.7 KB
    struct { float n2s[N]; float n2t[N]; float gsh[JT][BH];
             float4 sp[JT][N]; } f;                                   // ~38 KB
};

// ---------------- helpers ----------------
__device__ __forceinline__ const float* row_ptr(const float* q, const float* p, int r) {
    return (r < BH) ? (q + r * D) : (p + (r - BH) * D);
}

// block-wide sum, result broadcast to all threads (256-thread blocks).
__device__ __forceinline__ float block_sum_all(float v) {
    __shared__ float sbuf[9];
    __syncthreads();
    #pragma unroll
    for (int o = 16; o > 0; o >>= 1) v += __shfl_down_sync(0xffffffffu, v, o);
    int w = threadIdx.x >> 5, l = threadIdx.x & 31;
    if (l == 0) sbuf[w] = v;
    __syncthreads();
    if (threadIdx.x == 0) {
        float s = 0.0f;
        #pragma unroll
        for (int i = 0; i < 8; i++) s += sbuf[i];
        sbuf[8] = s;
    }
    __syncthreads();
    return sbuf[8];
}

// block-wide max, result broadcast.
__device__ __forceinline__ float block_max_all(float v) {
    __shared__ float mbuf[9];
    __syncthreads();
    #pragma unroll
    for (int o = 16; o > 0; o >>= 1) v = fmaxf(v, __shfl_down_sync(0xffffffffu, v, o));
    int w = threadIdx.x >> 5, l = threadIdx.x & 31;
    if (l == 0) mbuf[w] = v;
    __syncthreads();
    if (threadIdx.x == 0) {
        float s = -INFINITY;
        #pragma unroll
        for (int i = 0; i < 8; i++) s = fmaxf(s, mbuf[i]);
        mbuf[8] = s;
    }
    __syncthreads();
    return mbuf[8];
}

// Monotonic grid barrier: counts up forever; target = next multiple of NB.
// Graph-replay safe (no reset, no read-after-reset race).
__device__ __forceinline__ void grid_barrier(int idx) {
    __syncthreads();
    if (threadIdx.x == 0) {
        __threadfence();
        unsigned o = atomicAdd(&g_gbar[idx], 1u);
        unsigned target = (o & ~(unsigned)(NB - 1)) + (unsigned)NB;
        while (*(volatile unsigned*)&g_gbar[idx] < target) __nanosleep(64);
    }
    __syncthreads();
    __threadfence();
}

// ---------------- gram task (one 64x64 symmetric tile, one split chunk) ----------------
__device__ void gram_task(int task, SmemU* smem,
                          const float* __restrict__ sq, const float* __restrict__ sp,
                          const float* __restrict__ tq, const float* __restrict__ tp) {
    int x = task % NTILE;
    int y = task / NTILE;
    int mat = y >> 4;
    int split = y & 15;
    const float* q = mat ? tq : sq;
    const float* p = mat ? tp : sp;
    float* Gp = g_Gp[mat][split];

    int bx = TBX[x], by = TBY[x];
    int TI = bx * 64;
    int TK = by * 64;
    int tid = threadIdx.x;
    int tx = tid & 15, ty = tid >> 4;
    int lr = tid >> 2;
    int lc = (tid & 3) * 4;

    float acc[4][4];
    #pragma unroll
    for (int a = 0; a < 4; a++)
        #pragma unroll
        for (int b = 0; b < 4; b++) acc[a][b] = 0.0f;

    int k0base = split * CHUNK;
    const float* arow = row_ptr(q, p, TI + lr) + lc;
    const float* brow = row_ptr(q, p, TK + lr) + lc;

    float4 av = *(const float4*)(arow + k0base);
    float4 bv = *(const float4*)(brow + k0base);

    #pragma unroll
    for (int s = 0; s < NSTAGE; s++) {
        smem->g.As[lc + 0][lr] = av.x; smem->g.As[lc + 1][lr] = av.y;
        smem->g.As[lc + 2][lr] = av.z; smem->g.As[lc + 3][lr] = av.w;
        smem->g.Bs[lc + 0][lr] = bv.x; smem->g.Bs[lc + 1][lr] = bv.y;
        smem->g.Bs[lc + 2][lr] = bv.z; smem->g.Bs[lc + 3][lr] = bv.w;
        __syncthreads();
        if (s + 1 < NSTAGE) {
            av = *(const float4*)(arow + k0base + (s + 1) * TSTEP);
            bv = *(const float4*)(brow + k0base + (s + 1) * TSTEP);
        }
        #pragma unroll
        for (int kk = 0; kk < TSTEP; kk++) {
            float4 a = *(const float4*)&smem->g.As[kk][ty * 4];
            float4 b = *(const float4*)&smem->g.Bs[kk][tx * 4];
            acc[0][0] = fmaf(a.x, b.x, acc[0][0]);
            acc[0][1] = fmaf(a.x, b.y, acc[0][1]);
            acc[0][2] = fmaf(a.x, b.z, acc[0][2]);
            acc[0][3] = fmaf(a.x, b.w, acc[0][3]);
            acc[1][0] = fmaf(a.y, b.x, acc[1][0]);
            acc[1][1] = fmaf(a.y, b.y, acc[1][1]);
            acc[1][2] = fmaf(a.y, b.z, acc[1][2]);
            acc[1][3] = fmaf(a.y, b.w, acc[1][3]);
            acc[2][0] = fmaf(a.z, b.x, acc[2][0]);
            acc[2][1] = fmaf(a.z, b.y, acc[2][1]);
            acc[2][2] = fmaf(a.z, b.z, acc[2][2]);
            acc[2][3] = fmaf(a.z, b.w, acc[2][3]);
            acc[3][0] = fmaf(a.w, b.x, acc[3][0]);
            acc[3][1] = fmaf(a.w, b.y, acc[3][1]);
            acc[3][2] = fmaf(a.w, b.z, acc[3][2]);
            acc[3][3] = fmaf(a.w, b.w, acc[3][3]);
        }
        __syncthreads();
    }

    #pragma unroll
    for (int r = 0; r < 4; r++) {
        float4 v = make_float4(acc[r][0], acc[r][1], acc[r][2], acc[r][3]);
        *(float4*)&Gp[(TI + ty * 4 + r) * N + TK + tx * 4] = v;
    }
    if (bx != by) {
        #pragma unroll
        for (int c = 0; c < 4; c++) {
            float4 v = make_float4(acc[0][c], acc[1][c], acc[2][c], acc[3][c]);
            *(float4*)&Gp[(TK + tx * 4 + c) * N + TI + ty * 4] = v;
        }
    }
}

// ---------------- the single persistent kernel ----------------
__global__ void __launch_bounds__(256, 2) mono_kernel(
        const float* __restrict__ sq, const float* __restrict__ sp,
        const float* __restrict__ tq, const float* __restrict__ tp,
        float* __restrict__ out, int out_size) {
    __shared__ SmemU smem;
    int bid = blockIdx.x;
    int k = threadIdx.x;

    // ===== Phase A: gram (320 tasks over 256 blocks) =====
    gram_task(bid, &smem, sq, sp, tq, tp);
    if (bid < NTASKS - NB) gram_task(NB + bid, &smem, sq, sp, tq, tp);
    grid_barrier(0);

    // ===== Phase B: fold split-K for row bid of both matrices =====
    {
        int z = k >> 7;           // matrix
        int c = k & 127;          // 0..63 active (float4 lane)
        int row = bid;
        float4 s = make_float4(0.f, 0.f, 0.f, 0.f);
        if (c < 64) {
            #pragma unroll
            for (int pp = 0; pp < SPLITK; pp++) {
                float4 v = *(const float4*)(g_Gp[z][pp] + row * N + 4 * c);
                s.x += v.x; s.y += v.y; s.z += v.z; s.w += v.w;
            }
            *(float4*)((z ? g_Gt : g_Gs) + row * N + 4 * c) = s;
            if (c == (row >> 2)) {
                int comp = row & 3;
                float d = (comp == 0) ? s.x : (comp == 1) ? s.y : (comp == 2) ? s.z : s.w;
                (z ? g_n2t : g_n2s)[row] = d;
            }
        }
        float part = s.x + s.y + s.z + s.w;   // 0 for inactive threads
        #pragma unroll
        for (int o = 16; o > 0; o >>= 1) part += __shfl_down_sync(0xffffffffu, part, o);
        __shared__ float rbuf[8];
        if ((k & 31) == 0) rbuf[k >> 5] = part;
        __syncthreads();
        if (k == 0) {
            g_rowsum[0][row] = rbuf[0] + rbuf[1] + rbuf[2] + rbuf[3];
            g_rowsum[1][row] = rbuf[4] + rbuf[5] + rbuf[6] + rbuf[7];
        }
    }
    grid_barrier(1);

    // ===== Means (computed redundantly per block; broadcast in-register) =====
    float tr_s  = block_sum_all(g_n2s[k]);
    float tr_t  = block_sum_all(g_n2t[k]);
    float sum_s = block_sum_all(g_rowsum[0][k]);
    float sum_t = block_sum_all(g_rowsum[1][k]);
    float inv_ms = 1.0f / (((float)N * tr_s - sum_s) / CNT2 + EPSF);
    float inv_mt = 1.0f / (((float)N * tr_t - sum_t) / CNT2 + EPSF);

    // ===== Phase C: fused angle + dist + contrastive =====
    int joct = bid >> 3;
    int q = bid & 7;
    int jbase = joct * JT;

    float n2sk = g_n2s[k], n2tk = g_n2t[k];
    __syncthreads();          // smem union: done with any previous use
    smem.f.n2s[k] = n2sk; smem.f.n2t[k] = n2tk;
    float gsv[JT], gtv[JT];
    #pragma unroll
    for (int jj = 0; jj < JT; jj++) {
        gsv[jj] = g_Gs[(jbase + jj) * N + k];
        gtv[jj] = g_Gt[(jbase + jj) * N + k];
        if (k >= BH) smem.f.gsh[jj][k - BH] = gsv[jj];
    }
    __syncthreads();

    float rsk[JT], rtk[JT];
    #pragma unroll
    for (int jj = 0; jj < JT; jj++) {
        int j = jbase + jj;
        float ds = smem.f.n2s[j] + n2sk - 2.0f * gsv[jj];
        float dt = smem.f.n2t[j] + n2tk - 2.0f * gtv[jj];
        float rs = (k == j) ? 0.0f : 1.0f / (sqrtf(fmaxf(ds, 0.0f)) + EPSF);
        float rt = (k == j) ? 0.0f : 1.0f / (sqrtf(fmaxf(dt, 0.0f)) + EPSF);
        rsk[jj] = rs; rtk[jj] = rt;
        smem.f.sp[jj][k] = make_float4(rs, (smem.f.n2s[j] - gsv[jj]) * rs,
                                       rt, (smem.f.n2t[j] - gtv[jj]) * rt);
    }
    __syncthreads();

    // ---- dist huber + contrastive for j = jbase + q ----
    {
        int j = jbase + q;
        float ds = smem.f.n2s[j] + n2sk - 2.0f * gsv[q];
        float dt = smem.f.n2t[j] + n2tk - 2.0f * gtv[q];
        float v = 0.0f;
        if (k > j) {
            float diff = ds * inv_ms - dt * inv_mt;
            float a = fabsf(diff), m = fminf(a, 1.0f);
            v = 0.5f * m * (2.0f * a - m);
        }
        float sd = block_sum_all(v);
        if (k == 0) g_pdist[j] = sd;
        if (j < BH) {
            float sval = (k < BH) ? smem.f.gsh[q][k] : -INFINITY;
            float mx = block_max_all(sval);
            float ex = (k < BH) ? expf(INV_TEMP * (sval - mx)) : 0.0f;
            float sm = block_sum_all(ex);
            if (k == 0)
                g_pcl[j] = INV_TEMP * mx + logf(sm) - INV_TEMP * smem.f.gsh[q][j];
        }
    }

    // ---- angle loop: i > k (pair symmetry), comb q of 8 ----
    const float* __restrict__ Gsk = g_Gs + k;
    const float* __restrict__ Gtk = g_Gt + k;
    int wbase = k & ~31;
    float acc = 0.0f;
    #pragma unroll 2
    for (int i = wbase + 1 + q; i < N; i += 8) {
        float gsik = Gsk[i * N];
        float gtik = Gtk[i * N];
        float pred = (i > k) ? 1.0f : 0.0f;
        float hsum = 0.0f;
        #pragma unroll
        for (int jj = 0; jj < JT; jj++) {
            float4 c = smem.f.sp[jj][i];
            float us = fmaf(c.x, gsik - gsv[jj], c.y);
            float ut = fmaf(c.z, gtik - gtv[jj], c.w);
            float d  = fmaf(rtk[jj], -ut, rsk[jj] * us);  // cos_s - cos_t
            float a  = fabsf(d);
            float m  = fminf(a, 1.0f);
            hsum += m * fmaf(2.0f, a, -m);                // 2*huber
        }
        acc = fmaf(pred, hsum, acc);
    }
    float sa = block_sum_all(acc);
    if (k == 0) g_pang[bid] = sa;

    // ---- final ticket: last block combines and writes output ----
    __shared__ unsigned int stick;
    __threadfence();
    if (k == 0) stick = atomicAdd(&g_ctr2, 1);
    __syncthreads();
    if (stick == NB - 1) {
        __threadfence();
        float dsum  = block_sum_all(g_pdist[k]);
        float asum  = block_sum_all(g_pang[k]);
        float clsum = block_sum_all((k < BH) ? g_pcl[k] : 0.0f);
        if (k == 0) {
            float contrastive = clsum / (float)BH;
            float kd = 0.5f * (dsum / CNT2) + 0.5f * (asum / CNT3);
            if (out_size > 0) out[0] = contrastive + kd;
            if (out_size > 1) out[1] = contrastive;
            if (out_size > 2) out[2] = kd;
            g_ctr2 = 0;   // reset for next graph replay
        }
    }
}

// ---------------- launch ----------------
extern "C" void kernel_launch(void* const* d_in, const int* in_sizes, int n_in,
                              void* d_out, int out_size) {
    const float* sq = (const float*)d_in[0];
    const float* sp = (const float*)d_in[1];
    const float* tq = (const float*)d_in[2];
    const float* tp = (const float*)d_in[3];
    float* out = (float*)d_out;

    mono_kernel<<<NB, 256>>>(sq, sp, tq, tp, out, out_size);
}